// round 3
// baseline (speedup 1.0000x reference)
#include <cuda_runtime.h>
#include <cuda_bf16.h>
#include <cstdint>

#define IOU_EPS 1e-5f
#define B_  8
#define G_  64
#define P_  32768
#define C_  80

// Packed argmax results: high 32 bits = iou float bits (iou >= 0, order-preserving),
// low 32 bits = ~idx (so atomicMax prefers SMALLER idx on iou ties, matching jnp.argmax).
__device__ unsigned long long g_best_packed[B_ * G_];

__global__ void k_zero() {
    int i = blockIdx.x * blockDim.x + threadIdx.x;
    if (i < B_ * G_) g_best_packed[i] = 0ull;
}

// Kernel 1: per-gt argmax over all P predictions.
// grid = (8 chunks, 8 gt-subsets, 8 batches), 256 threads.
// Each block: 8 gts vs a 4096-pr chunk. Per-thread serial max over 16 prs x 8 gts,
// warp shfl reduce, lane0 does one division + atomicMax per gt.
__global__ void k_argmax(const float* __restrict__ gt, const float* __restrict__ pr) {
    const int b = blockIdx.z, gs = blockIdx.y, chunk = blockIdx.x;
    __shared__ float s_gy1[8], s_gx1[8], s_gy2[8], s_gx2[8], s_ga[8];
    __shared__ int   s_valid[8];
    const int t = threadIdx.x;
    if (t < 8) {
        const int g = gs * 8 + t;
        const float* row = gt + (b * G_ + g) * 6;
        float cx = row[0], cy = row[1], w = row[2], h = row[3];
        s_valid[t] = (cx != -1.0f);
        s_gy1[t] = cy - 0.5f * h;  s_gx1[t] = cx - 0.5f * w;
        s_gy2[t] = cy + 0.5f * h;  s_gx2[t] = cx + 0.5f * w;
        s_ga[t]  = w * h;
    }
    __syncthreads();

    float bi[8], bu[8]; int bx[8];
    #pragma unroll
    for (int g = 0; g < 8; g++) { bi[g] = -1.0f; bu[g] = 0.0f; bx[g] = 0x7FFFFFFF; }

    const int pbase = chunk * 4096 + t;
    #pragma unroll 4
    for (int i = 0; i < 16; i++) {
        const int p = pbase + i * 256;
        const float4 pb = reinterpret_cast<const float4*>(pr)[p];
        const float py1 = pb.y - 0.5f * pb.w, px1 = pb.x - 0.5f * pb.z;
        const float py2 = pb.y + 0.5f * pb.w, px2 = pb.x + 0.5f * pb.z;
        const float pa  = pb.z * pb.w;
        #pragma unroll
        for (int g = 0; g < 8; g++) {
            if (!s_valid[g]) continue;
            float ih = fmaxf(fminf(s_gy2[g], py2) - fmaxf(s_gy1[g], py1), 0.0f);
            float iw = fmaxf(fminf(s_gx2[g], px2) - fmaxf(s_gx1[g], px1), 0.0f);
            float inter = iw * ih;
            float un = s_ga[g] + pa - inter;
            // compare inter/(un+eps) vs bi/(bu+eps) via cross-multiplication (no div)
            float lhs = inter * (bu[g] + IOU_EPS);
            float rhs = bi[g] * (un + IOU_EPS);
            if (lhs > rhs || (lhs == rhs && p < bx[g])) { bi[g] = inter; bu[g] = un; bx[g] = p; }
        }
    }

    const unsigned FULL = 0xFFFFFFFFu;
    #pragma unroll
    for (int g = 0; g < 8; g++) {
        float i0 = bi[g], u0 = bu[g]; int x0 = bx[g];
        #pragma unroll
        for (int off = 16; off; off >>= 1) {
            float oi = __shfl_down_sync(FULL, i0, off);
            float ou = __shfl_down_sync(FULL, u0, off);
            int   ox = __shfl_down_sync(FULL, x0, off);
            float lhs = oi * (u0 + IOU_EPS);
            float rhs = i0 * (ou + IOU_EPS);
            if (lhs > rhs || (lhs == rhs && ox < x0)) { i0 = oi; u0 = ou; x0 = ox; }
        }
        if ((t & 31) == 0 && s_valid[g] && i0 >= 0.0f) {
            float iou = __fdiv_rn(i0, u0 + IOU_EPS);   // IEEE div, matches JAX value
            unsigned long long packed =
                ((unsigned long long)__float_as_uint(iou) << 32) | (unsigned)(~x0);
            atomicMax(&g_best_packed[b * G_ + gs * 8 + g], packed);
        }
    }
}

// Kernel 2: per-(b,p) assignment + output write.
// grid = (128, 8), 256 threads. One thread per prediction.
__global__ void k_main(const float* __restrict__ gt, const float* __restrict__ pr,
                       float* __restrict__ out) {
    const int b = blockIdx.y;
    const int p = blockIdx.x * 256 + threadIdx.x;
    const int t = threadIdx.x;

    __shared__ float4 s_a[G_];  // gy1, gx1, gy2, gx2
    __shared__ float4 s_b[G_];  // ga, cx, cy, log(w)
    __shared__ float4 s_c[G_];  // log(h), label, bestp (int bits), valid

    if (t < G_) {
        const float* row = gt + (b * G_ + t) * 6;
        float cx = row[0], cy = row[1], w = row[2], h = row[3];
        float lab = row[4], conf = row[5];
        int valid = (cx != -1.0f);
        unsigned long long pk = g_best_packed[b * G_ + t];
        int bp = (int)(~(unsigned)(pk & 0xFFFFFFFFull));
        if (!valid || !(conf > 0.0f)) bp = -1;   // "best" requires conf > 0
        s_a[t] = make_float4(cy - 0.5f * h, cx - 0.5f * w, cy + 0.5f * h, cx + 0.5f * w);
        float lw = (w > 0.0f) ? logf(fmaxf(w, 1e-20f)) : 0.0f;
        float lh = (h > 0.0f) ? logf(fmaxf(h, 1e-20f)) : 0.0f;
        s_b[t] = make_float4(w * h, cx, cy, lw);
        s_c[t] = make_float4(lh, lab, __int_as_float(bp), valid ? 1.0f : 0.0f);
    }
    __syncthreads();

    const float4 pb = reinterpret_cast<const float4*>(pr)[p];  // pr_boxes[0] region
    const float py1 = pb.y - 0.5f * pb.w, px1 = pb.x - 0.5f * pb.z;
    const float py2 = pb.y + 0.5f * pb.w, px2 = pb.x + 0.5f * pb.z;
    const float pa  = pb.z * pb.w;

    float W = 0.0f, Scx = 0.0f, Scy = 0.0f, Slw = 0.0f, Slh = 0.0f;
    int gth = -1, gbe = -1;
    bool ignore = false;

    #pragma unroll 8
    for (int g = 0; g < G_; g++) {
        const float4 a  = s_a[g];
        const float4 bb = s_b[g];
        const float4 cc = s_c[g];
        if (cc.w == 0.0f) continue;   // invalid gt: masked iou = 0, contributes nothing
        float ih = fmaxf(fminf(a.z, py2) - fmaxf(a.x, py1), 0.0f);
        float iw = fmaxf(fminf(a.w, px2) - fmaxf(a.y, px1), 0.0f);
        float inter = iw * ih;
        float d = (bb.x + pa - inter) + IOU_EPS;
        bool th = inter >= 0.5f * d;          // iou >= 0.5
        bool ig = inter >= 0.4f * d;          // iou >= 0.4
        bool be = (__float_as_int(cc.z) == p);
        if (th) gth = g;
        if (be) gbe = g;
        ignore |= (ig && !th);
        float wgt = (th ? 1.0f : 0.0f) + (be ? 1.0f : 0.0f);
        W   += wgt;
        Scx += wgt * bb.y;
        Scy += wgt * bb.z;
        Slw += wgt * bb.w;
        Slh += wgt * cc.x;
    }

    const int win = (gbe >= 0) ? gbe : gth;
    const bool matched = (win >= 0);
    int cid = C_;
    if (matched) cid = (int)s_c[win].y;
    const float mask = ignore ? -1.0f : (matched ? 0.0f : 1.0f);

    const float hcx = __fdividef(Scx - W * pb.x, pb.z);
    const float hcy = __fdividef(Scy - W * pb.y, pb.w);
    const float hw  = Slw - W * __logf(pb.z);
    const float hh  = Slh - W * __logf(pb.w);

    const long long CLS_SZ = (long long)B_ * P_ * C_;
    const long long LOC_SZ = (long long)B_ * P_ * 4;
    const long long bp_ = (long long)b * P_ + p;

    // loc_true: coalesced float4 per thread
    reinterpret_cast<float4*>(out + CLS_SZ)[bp_] = make_float4(hcx, hcy, hw, hh);
    // assign_mask: coalesced float per thread
    out[CLS_SZ + LOC_SZ + bp_] = mask;

    // cls_true: warp-cooperative coalesced write of 32 one-hot rows (32*80 floats = 640 float4)
    const int lane = t & 31;
    const long long rowbase = (long long)b * P_ + (p & ~31);
    float4* cbase = reinterpret_cast<float4*>(out + rowbase * C_);
    #pragma unroll
    for (int i = 0; i < 20; i++) {
        int f4  = i * 32 + lane;          // 0..639
        int row = f4 / 20;                // 0..31 (20 float4 per 80-float row)
        int col = (f4 - row * 20) * 4;    // 0,4,...,76
        int cid_r = __shfl_sync(0xFFFFFFFFu, cid, row);
        float4 v;
        v.x = (col     == cid_r) ? 1.0f : 0.0f;
        v.y = (col + 1 == cid_r) ? 1.0f : 0.0f;
        v.z = (col + 2 == cid_r) ? 1.0f : 0.0f;
        v.w = (col + 3 == cid_r) ? 1.0f : 0.0f;
        cbase[f4] = v;
    }
}

extern "C" void kernel_launch(void* const* d_in, const int* in_sizes, int n_in,
                              void* d_out, int out_size) {
    const float* gt = (const float*)d_in[0];   // [8, 64, 6]
    const float* pr = (const float*)d_in[1];   // [8, 32768, 4] (broadcast; batch 0 used)
    float* out = (float*)d_out;                // cls[8,32768,80] | loc[8,32768,4] | mask[8,32768,1]

    k_zero<<<2, 256>>>();
    k_argmax<<<dim3(8, 8, 8), 256>>>(gt, pr);
    k_main<<<dim3(P_ / 256, B_), 256>>>(gt, pr, out);
}

// round 6
// speedup vs baseline: 1.2420x; 1.2420x over previous
#include <cuda_runtime.h>
#include <cuda_bf16.h>
#include <cstdint>

#define IOU_EPS 1e-5f
#define B_  8
#define G_  64
#define P_  32768
#define C_  80
#define NCHUNK 16
#define CHUNK_P (P_ / NCHUNK)   // 2048

// Per-chunk argmax partials. packed = (iou_bits << 32) | ~idx  (u64 max => max iou,
// tie -> smaller idx, matching jnp.argmax first-index tie-break). 0 == "no candidate".
__device__ unsigned long long g_part[B_ * G_ * NCHUNK];

// Kernel 1: per-gt argmax over a 2048-prediction chunk. grid=(16,8,8), 256 thr.
__global__ void k_argmax(const float* __restrict__ gt, const float* __restrict__ pr) {
    const int b = blockIdx.z, gs = blockIdx.y, chunk = blockIdx.x;
    const int t = threadIdx.x, lane = t & 31, wid = t >> 5;
    __shared__ float s_gy1[8], s_gx1[8], s_gy2[8], s_gx2[8], s_ga[8];
    __shared__ int   s_valid[8];
    __shared__ float r_i[8][8], r_u[8][8];
    __shared__ int   r_x[8][8];

    if (t < 8) {
        const int g = gs * 8 + t;
        const float* row = gt + (b * G_ + g) * 6;
        float cx = row[0], cy = row[1], w = row[2], h = row[3];
        s_valid[t] = (cx != -1.0f);
        s_gy1[t] = cy - 0.5f * h;  s_gx1[t] = cx - 0.5f * w;
        s_gy2[t] = cy + 0.5f * h;  s_gx2[t] = cx + 0.5f * w;
        s_ga[t]  = w * h;
    }
    __syncthreads();

    const int any = s_valid[0] | s_valid[1] | s_valid[2] | s_valid[3]
                  | s_valid[4] | s_valid[5] | s_valid[6] | s_valid[7];
    if (!any) {   // whole 8-gt group invalid: write empty slots, done
        if (t < 8)
            g_part[(b * G_ + gs * 8 + t) * NCHUNK + chunk] = 0ull;
        return;
    }

    float bi[8], bu[8]; int bx[8];
    #pragma unroll
    for (int g = 0; g < 8; g++) { bi[g] = -1.0f; bu[g] = 0.0f; bx[g] = 0x7FFFFFFF; }

    const int pbase = chunk * CHUNK_P + t;
    #pragma unroll
    for (int i = 0; i < CHUNK_P / 256; i++) {
        const int p = pbase + i * 256;
        const float4 pb = reinterpret_cast<const float4*>(pr)[p];
        const float py1 = pb.y - 0.5f * pb.w, px1 = pb.x - 0.5f * pb.z;
        const float py2 = pb.y + 0.5f * pb.w, px2 = pb.x + 0.5f * pb.z;
        const float pa  = pb.z * pb.w;
        #pragma unroll
        for (int g = 0; g < 8; g++) {
            if (!s_valid[g]) continue;
            float ih = fmaxf(fminf(s_gy2[g], py2) - fmaxf(s_gy1[g], py1), 0.0f);
            float iw = fmaxf(fminf(s_gx2[g], px2) - fmaxf(s_gx1[g], px1), 0.0f);
            float inter = iw * ih;
            float un = s_ga[g] + pa - inter;
            // compare inter/(un+eps) vs bi/(bu+eps) via cross-multiplication (no div)
            float lhs = inter * (bu[g] + IOU_EPS);
            float rhs = bi[g] * (un + IOU_EPS);
            if (lhs > rhs || (lhs == rhs && p < bx[g])) { bi[g] = inter; bu[g] = un; bx[g] = p; }
        }
    }

    const unsigned FULL = 0xFFFFFFFFu;
    #pragma unroll
    for (int g = 0; g < 8; g++) {
        float i0 = bi[g], u0 = bu[g]; int x0 = bx[g];
        #pragma unroll
        for (int off = 16; off; off >>= 1) {
            float oi = __shfl_down_sync(FULL, i0, off);
            float ou = __shfl_down_sync(FULL, u0, off);
            int   ox = __shfl_down_sync(FULL, x0, off);
            float lhs = oi * (u0 + IOU_EPS);
            float rhs = i0 * (ou + IOU_EPS);
            if (lhs > rhs || (lhs == rhs && ox < x0)) { i0 = oi; u0 = ou; x0 = ox; }
        }
        if (lane == 0) { r_i[g][wid] = i0; r_u[g][wid] = u0; r_x[g][wid] = x0; }
    }
    __syncthreads();

    if (t < 8) {
        unsigned long long outv = 0ull;
        if (s_valid[t]) {
            float i0 = r_i[t][0], u0 = r_u[t][0]; int x0 = r_x[t][0];
            #pragma unroll
            for (int w2 = 1; w2 < 8; w2++) {
                float oi = r_i[t][w2], ou = r_u[t][w2]; int ox = r_x[t][w2];
                float lhs = oi * (u0 + IOU_EPS);
                float rhs = i0 * (ou + IOU_EPS);
                if (lhs > rhs || (lhs == rhs && ox < x0)) { i0 = oi; u0 = ou; x0 = ox; }
            }
            float iou = __fdiv_rn(i0, u0 + IOU_EPS);   // IEEE div, matches JAX value
            outv = ((unsigned long long)__float_as_uint(iou) << 32) | (unsigned)(~x0);
        }
        g_part[(b * G_ + gs * 8 + t) * NCHUNK + chunk] = outv;
    }
}

// Kernel 2: per-(b,p) assignment + output write. grid=(128,8), 256 thr.
// Valid gts compacted (ballot prefix). best_p inverted into a per-prediction
// BITMASK (s_gbe) so multiple gts sharing one best prediction all contribute
// weight (reference: w = thresh + best, summed over g).
__global__ void k_main(const float* __restrict__ gt, const float* __restrict__ pr,
                       float* __restrict__ out) {
    const int b = blockIdx.y;
    const int p0 = blockIdx.x * 256;
    const int t = threadIdx.x, lane = t & 31;
    const int p = p0 + t;

    __shared__ float4 sa[G_];     // gy1, gx1, gy2, gx2
    __shared__ float4 sbv[G_];    // ga, cx, cy, log(w)
    __shared__ float  slh[G_];    // log(h)
    __shared__ float  slab[G_];   // label
    __shared__ int    s_wcnt[2], s_cnt;
    __shared__ unsigned long long s_gbe[256]; // bitmask of compacted gts whose best_p == local p

    s_gbe[t] = 0ull;

    float4 rowa; float ga = 0.f, gcx = 0.f, gcy = 0.f, lw = 0.f, lh = 0.f, lab = 0.f;
    int validf = 0, bp = -1, pos = 0;
    if (t < G_) {
        const float* row = gt + (b * G_ + t) * 6;
        float cx = row[0], cy = row[1], w = row[2], h = row[3];
        lab = row[4]; float conf = row[5];
        validf = (cx != -1.0f);
        rowa = make_float4(cy - 0.5f * h, cx - 0.5f * w, cy + 0.5f * h, cx + 0.5f * w);
        ga = w * h; gcx = cx; gcy = cy;
        lw = (w > 0.0f) ? logf(fmaxf(w, 1e-20f)) : 0.0f;
        lh = (h > 0.0f) ? logf(fmaxf(h, 1e-20f)) : 0.0f;
        // reduce the 16 chunk partials -> global best_p for this gt
        unsigned long long best = 0ull;
        const unsigned long long* pp = g_part + (b * G_ + t) * NCHUNK;
        #pragma unroll
        for (int c = 0; c < NCHUNK; c++) {
            unsigned long long v = pp[c];
            best = (v > best) ? v : best;
        }
        bp = (int)(~(unsigned)(best & 0xFFFFFFFFull));   // empty -> -1
        if (!validf || !(conf > 0.0f)) bp = -1;          // "best" requires conf > 0
        // compaction prefix within warp
        unsigned m = __ballot_sync(0xFFFFFFFFu, validf);
        pos = __popc(m & ((1u << lane) - 1));
        if (lane == 0) s_wcnt[t >> 5] = __popc(m);
    }
    __syncthreads();
    if (t < G_ && validf) {
        int j = ((t >= 32) ? s_wcnt[0] : 0) + pos;   // compaction is g-order-preserving
        sa[j]  = rowa;
        sbv[j] = make_float4(ga, gcx, gcy, lw);
        slh[j] = lh;
        slab[j] = lab;
        if (bp >= p0 && bp < p0 + 256) atomicOr(&s_gbe[bp - p0], 1ull << j);
    }
    if (t == 0) s_cnt = s_wcnt[0] + s_wcnt[1];
    __syncthreads();

    const float4 pb = reinterpret_cast<const float4*>(pr)[p];
    const float py1 = pb.y - 0.5f * pb.w, px1 = pb.x - 0.5f * pb.z;
    const float py2 = pb.y + 0.5f * pb.w, px2 = pb.x + 0.5f * pb.z;
    const float pa  = pb.z * pb.w;

    float W = 0.0f, Scx = 0.0f, Scy = 0.0f, Slw = 0.0f, Slh = 0.0f;
    int gth = -1;
    bool ignore = false;
    const int cnt = s_cnt;

    #pragma unroll 8
    for (int j = 0; j < cnt; j++) {
        const float4 a  = sa[j];
        const float4 bb = sbv[j];
        const float lhj = slh[j];
        float ih = fmaxf(fminf(a.z, py2) - fmaxf(a.x, py1), 0.0f);
        float iw = fmaxf(fminf(a.w, px2) - fmaxf(a.y, px1), 0.0f);
        float inter = iw * ih;
        float d = ((bb.x + pa) - inter) + IOU_EPS;   // union + eps, reference op order
        bool th = inter >= 0.5f * d;                 // iou >= 0.5 (exact x0.5)
        bool ig = inter >= 0.4f * d;                 // iou >= 0.4 (R3-proven form)
        if (th) { gth = j; W += 1.0f; Scx += bb.y; Scy += bb.z; Slw += bb.w; Slh += lhj; }
        ignore |= (ig && !th);
    }

    // best-box contributions: ALL gts whose best_p == p add weight (can be >1)
    unsigned long long bm = s_gbe[t];
    int gbe = -1;
    if (bm) {
        gbe = 63 - __clzll(bm);           // winner = max compacted j = max g
        do {
            int j = __ffsll(bm) - 1;
            bm &= bm - 1;
            const float4 bb = sbv[j];
            W += 1.0f; Scx += bb.y; Scy += bb.z; Slw += bb.w; Slh += slh[j];
        } while (bm);
    }

    const int win = (gbe >= 0) ? gbe : gth;
    const bool matched = (win >= 0);
    const int widx = matched ? win : 0;
    const int cid = matched ? (int)slab[widx] : C_;
    const float mask = ignore ? -1.0f : (matched ? 0.0f : 1.0f);

    const float hcx = __fdividef(Scx - W * pb.x, pb.z);
    const float hcy = __fdividef(Scy - W * pb.y, pb.w);
    const float hw  = Slw - W * __logf(pb.z);
    const float hh  = Slh - W * __logf(pb.w);

    const long long CLS_SZ = (long long)B_ * P_ * C_;
    const long long LOC_SZ = (long long)B_ * P_ * 4;
    const long long bp_ = (long long)b * P_ + p;

    // loc_true: coalesced float4 per thread
    reinterpret_cast<float4*>(out + CLS_SZ)[bp_] = make_float4(hcx, hcy, hw, hh);
    // assign_mask: coalesced float per thread
    out[CLS_SZ + LOC_SZ + bp_] = mask;

    // cls_true: warp-cooperative coalesced write of 32 one-hot rows (640 float4)
    const long long rowbase = (long long)b * P_ + (p & ~31);
    float4* cbase = reinterpret_cast<float4*>(out + rowbase * C_);
    #pragma unroll
    for (int i = 0; i < 20; i++) {
        int f4  = i * 32 + lane;          // 0..639
        int row = f4 / 20;                // 0..31 (20 float4 per 80-float row)
        int col = (f4 - row * 20) * 4;    // 0,4,...,76
        int cid_r = __shfl_sync(0xFFFFFFFFu, cid, row);
        float4 v;
        v.x = (col     == cid_r) ? 1.0f : 0.0f;
        v.y = (col + 1 == cid_r) ? 1.0f : 0.0f;
        v.z = (col + 2 == cid_r) ? 1.0f : 0.0f;
        v.w = (col + 3 == cid_r) ? 1.0f : 0.0f;
        cbase[f4] = v;
    }
}

extern "C" void kernel_launch(void* const* d_in, const int* in_sizes, int n_in,
                              void* d_out, int out_size) {
    const float* gt = (const float*)d_in[0];   // [8, 64, 6]
    const float* pr = (const float*)d_in[1];   // [8, 32768, 4] (broadcast; batch 0 used)
    float* out = (float*)d_out;                // cls[8,32768,80] | loc[8,32768,4] | mask[8,32768,1]

    k_argmax<<<dim3(NCHUNK, 8, 8), 256>>>(gt, pr);
    k_main<<<dim3(P_ / 256, B_), 256>>>(gt, pr, out);
}

// round 8
// speedup vs baseline: 1.3582x; 1.0936x over previous
#include <cuda_runtime.h>
#include <cuda_bf16.h>
#include <cstdint>

#define IOU_EPS 1e-5f
#define B_  8
#define G_  64
#define P_  32768
#define C_  80
#define NCHUNK 16
#define CHUNK_P (P_ / NCHUNK)   // 2048

// Per-chunk argmax partials. packed = (iou_bits << 32) | ~idx  (u64 max => max iou,
// tie -> smaller idx, matching jnp.argmax first-index tie-break). 0 == "no candidate".
__device__ unsigned long long g_part[B_ * G_ * NCHUNK];
// Per-(b,p) threshold masks: bit g of g_thm = (iou(b,g,p) >= 0.5), g_igm = (iou >= 0.4).
// Written one byte per gs-slice (byte gs holds gts gs*8..gs*8+7 -> bit position g).
__device__ unsigned long long g_thm[B_ * P_];
__device__ unsigned long long g_igm[B_ * P_];

// Pass 1: grid=(16,8,8)=(chunk,gs,b), 256 thr. Per block: 8 gts x 2048 prs.
// Computes per-gt argmax partials AND per-(p,gs) th/ig mask bytes.
__global__ void __launch_bounds__(256) k_pass1(const float* __restrict__ gt,
                                               const float* __restrict__ pr) {
    const int b = blockIdx.z, gs = blockIdx.y, chunk = blockIdx.x;
    const int t = threadIdx.x, lane = t & 31, wid = t >> 5;
    __shared__ float s_gy1[8], s_gx1[8], s_gy2[8], s_gx2[8], s_ga[8];
    __shared__ int   s_valid[8];
    __shared__ float r_i[8][8], r_u[8][8];
    __shared__ int   r_x[8][8];

    if (t < 8) {
        const int g = gs * 8 + t;
        const float* row = gt + (b * G_ + g) * 6;
        float cx = row[0], cy = row[1], w = row[2], h = row[3];
        s_valid[t] = (cx != -1.0f);
        s_gy1[t] = cy - 0.5f * h;  s_gx1[t] = cx - 0.5f * w;
        s_gy2[t] = cy + 0.5f * h;  s_gx2[t] = cx + 0.5f * w;
        s_ga[t]  = w * h;
    }
    __syncthreads();

    unsigned vmask = 0;
    #pragma unroll
    for (int g = 0; g < 8; g++) vmask |= (s_valid[g] ? (1u << g) : 0u);

    const int pbase = chunk * CHUNK_P + t;
    unsigned char* thm8 = (unsigned char*)g_thm;
    unsigned char* igm8 = (unsigned char*)g_igm;

    if (vmask == 0) {   // whole 8-gt slice invalid: masks are zero, no argmax work
        #pragma unroll
        for (int i = 0; i < CHUNK_P / 256; i++) {
            const long long p = pbase + i * 256;
            const long long byteoff = ((long long)b * P_ + p) * 8 + gs;
            thm8[byteoff] = 0; igm8[byteoff] = 0;
        }
        if (t < 8) g_part[(b * G_ + gs * 8 + t) * NCHUNK + chunk] = 0ull;
        return;
    }

    float bi[8], bueps[8]; int bx[8];
    #pragma unroll
    for (int g = 0; g < 8; g++) { bi[g] = -1.0f; bueps[g] = IOU_EPS; bx[g] = 0; }

    #pragma unroll
    for (int i = 0; i < CHUNK_P / 256; i++) {
        const int p = pbase + i * 256;
        const float4 pb = reinterpret_cast<const float4*>(pr)[p];
        const float py1 = pb.y - 0.5f * pb.w, px1 = pb.x - 0.5f * pb.z;
        const float py2 = pb.y + 0.5f * pb.w, px2 = pb.x + 0.5f * pb.z;
        const float pa  = pb.z * pb.w;
        unsigned thb = 0, igb = 0;
        #pragma unroll
        for (int g = 0; g < 8; g++) {
            float ih = fmaxf(fminf(s_gy2[g], py2) - fmaxf(s_gy1[g], py1), 0.0f);
            float iw = fmaxf(fminf(s_gx2[g], px2) - fmaxf(s_gx1[g], px1), 0.0f);
            float inter = iw * ih;
            float un = (s_ga[g] + pa) - inter;       // reference op order
            float uneps = un + IOU_EPS;
            if (inter >= 0.5f * uneps) thb |= 1u << g;   // iou >= 0.5 (R6-proven form)
            if (inter >= 0.4f * uneps) igb |= 1u << g;   // iou >= 0.4 (R6-proven form)
            // argmax via cross-mult; strict > with ascending p == first-max tie-break
            float lhs = inter * bueps[g];
            float rhs = bi[g] * uneps;
            if (lhs > rhs) { bi[g] = inter; bueps[g] = uneps; bx[g] = p; }
        }
        thb &= vmask; igb &= vmask;
        const long long byteoff = ((long long)b * P_ + p) * 8 + gs;
        thm8[byteoff] = (unsigned char)thb;
        igm8[byteoff] = (unsigned char)igb;
    }

    const unsigned FULL = 0xFFFFFFFFu;
    #pragma unroll
    for (int g = 0; g < 8; g++) {
        float i0 = bi[g], u0 = bueps[g]; int x0 = bx[g];
        #pragma unroll
        for (int off = 16; off; off >>= 1) {
            float oi = __shfl_down_sync(FULL, i0, off);
            float ou = __shfl_down_sync(FULL, u0, off);
            int   ox = __shfl_down_sync(FULL, x0, off);
            float lhs = oi * u0;
            float rhs = i0 * ou;
            if (lhs > rhs || (lhs == rhs && ox < x0)) { i0 = oi; u0 = ou; x0 = ox; }
        }
        if (lane == 0) { r_i[g][wid] = i0; r_u[g][wid] = u0; r_x[g][wid] = x0; }
    }
    __syncthreads();

    if (t < 8) {
        unsigned long long outv = 0ull;
        if (s_valid[t]) {
            float i0 = r_i[t][0], u0 = r_u[t][0]; int x0 = r_x[t][0];
            #pragma unroll
            for (int w2 = 1; w2 < 8; w2++) {
                float oi = r_i[t][w2], ou = r_u[t][w2]; int ox = r_x[t][w2];
                float lhs = oi * u0;
                float rhs = i0 * ou;
                if (lhs > rhs || (lhs == rhs && ox < x0)) { i0 = oi; u0 = ou; x0 = ox; }
            }
            float iou = __fdiv_rn(i0, u0);   // u0 already = union + eps; IEEE div
            outv = ((unsigned long long)__float_as_uint(iou) << 32) | (unsigned)(~x0);
        }
        g_part[(b * G_ + gs * 8 + t) * NCHUNK + chunk] = outv;
    }
}

// Pass 2: grid=(128,8), 256 thr. No gt loop — masks + sparse bit walks + output.
__global__ void __launch_bounds__(256) k_out(const float* __restrict__ gt,
                                             const float* __restrict__ pr,
                                             float* __restrict__ out) {
    const int b = blockIdx.y;
    const int p0 = blockIdx.x * 256;
    const int t = threadIdx.x, lane = t & 31;
    const int p = p0 + t;

    __shared__ float scx[G_], scy[G_], slw[G_], slhh[G_], slabv[G_];
    __shared__ unsigned long long s_gbe[256];   // bitmask of gts whose best_p == local p

    s_gbe[t] = 0ull;

    int bp = -1;
    if (t < G_) {
        const float* row = gt + (b * G_ + t) * 6;
        float cx = row[0], cy = row[1], w = row[2], h = row[3];
        float lab = row[4], conf = row[5];
        int validf = (cx != -1.0f);
        scx[t] = cx; scy[t] = cy;
        slw[t]  = (w > 0.0f) ? logf(fmaxf(w, 1e-20f)) : 0.0f;
        slhh[t] = (h > 0.0f) ? logf(fmaxf(h, 1e-20f)) : 0.0f;
        slabv[t] = lab;
        // reduce the 16 chunk partials -> global best_p for this gt
        unsigned long long best = 0ull;
        const unsigned long long* pp = g_part + (b * G_ + t) * NCHUNK;
        #pragma unroll
        for (int c = 0; c < NCHUNK; c++) {
            unsigned long long v = pp[c];
            best = (v > best) ? v : best;
        }
        bp = (int)(~(unsigned)(best & 0xFFFFFFFFull));   // empty -> -1
        if (!validf || !(conf > 0.0f)) bp = -1;          // "best" requires conf > 0
    }
    __syncthreads();
    if (t < G_ && bp >= p0 && bp < p0 + 256) atomicOr(&s_gbe[bp - p0], 1ull << t);
    __syncthreads();

    const long long bp_ = (long long)b * P_ + p;
    const unsigned long long th64 = g_thm[bp_];
    const unsigned long long ig64 = g_igm[bp_];
    const float4 pb = reinterpret_cast<const float4*>(pr)[p];

    const bool ignore = (ig64 & ~th64) != 0ull;

    float W = 0.0f, Scx = 0.0f, Scy = 0.0f, Slw = 0.0f, Slh = 0.0f;
    int gth = -1;
    unsigned long long m = th64;
    if (m) {
        gth = 63 - __clzll(m);
        do {
            int g = __ffsll(m) - 1;
            m &= m - 1;
            W += 1.0f; Scx += scx[g]; Scy += scy[g]; Slw += slw[g]; Slh += slhh[g];
        } while (m);
    }

    // best-box contributions: ALL gts whose best_p == p add weight (can be >1)
    unsigned long long bm = s_gbe[t];
    int gbe = -1;
    if (bm) {
        gbe = 63 - __clzll(bm);           // winner = max g
        do {
            int g = __ffsll(bm) - 1;
            bm &= bm - 1;
            W += 1.0f; Scx += scx[g]; Scy += scy[g]; Slw += slw[g]; Slh += slhh[g];
        } while (bm);
    }

    const int win = (gbe >= 0) ? gbe : gth;
    const bool matched = (win >= 0);
    const int widx = matched ? win : 0;
    const int cid = matched ? (int)slabv[widx] : C_;
    const float mask = ignore ? -1.0f : (matched ? 0.0f : 1.0f);

    const float hcx = __fdividef(Scx - W * pb.x, pb.z);
    const float hcy = __fdividef(Scy - W * pb.y, pb.w);
    const float hw  = Slw - W * __logf(pb.z);
    const float hh  = Slh - W * __logf(pb.w);

    const long long CLS_SZ = (long long)B_ * P_ * C_;
    const long long LOC_SZ = (long long)B_ * P_ * 4;

    // loc_true: coalesced float4 per thread
    reinterpret_cast<float4*>(out + CLS_SZ)[bp_] = make_float4(hcx, hcy, hw, hh);
    // assign_mask: coalesced float per thread
    out[CLS_SZ + LOC_SZ + bp_] = mask;

    // cls_true: warp-cooperative coalesced write of 32 one-hot rows (640 float4)
    const long long rowbase = (long long)b * P_ + (p & ~31);
    float4* cbase = reinterpret_cast<float4*>(out + rowbase * C_);
    #pragma unroll
    for (int i = 0; i < 20; i++) {
        int f4  = i * 32 + lane;          // 0..639
        int row = f4 / 20;                // 0..31 (20 float4 per 80-float row)
        int col = (f4 - row * 20) * 4;    // 0,4,...,76
        int cid_r = __shfl_sync(0xFFFFFFFFu, cid, row);
        float4 v;
        v.x = (col     == cid_r) ? 1.0f : 0.0f;
        v.y = (col + 1 == cid_r) ? 1.0f : 0.0f;
        v.z = (col + 2 == cid_r) ? 1.0f : 0.0f;
        v.w = (col + 3 == cid_r) ? 1.0f : 0.0f;
        cbase[f4] = v;
    }
}

extern "C" void kernel_launch(void* const* d_in, const int* in_sizes, int n_in,
                              void* d_out, int out_size) {
    const float* gt = (const float*)d_in[0];   // [8, 64, 6]
    const float* pr = (const float*)d_in[1];   // [8, 32768, 4] (broadcast; batch 0 used)
    float* out = (float*)d_out;                // cls[8,32768,80] | loc[8,32768,4] | mask[8,32768,1]

    k_pass1<<<dim3(NCHUNK, 8, 8), 256>>>(gt, pr);
    k_out<<<dim3(P_ / 256, B_), 256>>>(gt, pr, out);
}

// round 9
// speedup vs baseline: 1.5008x; 1.1050x over previous
#include <cuda_runtime.h>
#include <cuda_bf16.h>
#include <cstdint>

#define IOU_EPS 1e-5f
#define B_  8
#define G_  64
#define P_  32768
#define C_  80
#define NCHUNK 16
#define CHUNK_P (P_ / NCHUNK)   // 2048

// Per-chunk argmax partials. packed = (iou_bits << 32) | ~idx  (u64 max => max iou,
// tie -> smaller idx, matching jnp.argmax first-index tie-break). 0 == "no candidate".
__device__ unsigned long long g_part[B_ * G_ * NCHUNK];
// Per-(b,p) threshold masks: bit g of g_thm = (iou(b,g,p) >= 0.5), g_igm = (iou >= 0.4).
// Written one byte per gs-slice (byte gs holds gts gs*8..gs*8+7 -> bit position g).
__device__ unsigned long long g_thm[B_ * P_];
__device__ unsigned long long g_igm[B_ * P_];

// Pass 1: grid=(16,8,8)=(chunk,gs,b), 256 thr. Per block: 8 gts x 2048 prs.
// Computes per-gt argmax partials AND per-(p,gs) th/ig mask bytes, AND zero-fills
// this block's 80KB slice of the cls_true output (overlaps stores under compute;
// cls is ~99% zeros, k_out writes only the sparse 1.0 entries).
__global__ void __launch_bounds__(256) k_pass1(const float* __restrict__ gt,
                                               const float* __restrict__ pr,
                                               float* __restrict__ out) {
    const int b = blockIdx.z, gs = blockIdx.y, chunk = blockIdx.x;
    const int t = threadIdx.x, lane = t & 31, wid = t >> 5;
    __shared__ float s_gy1[8], s_gx1[8], s_gy2[8], s_gx2[8], s_ga[8];
    __shared__ int   s_valid[8];
    __shared__ float r_i[8][8], r_u[8][8];
    __shared__ int   r_x[8][8];

    // ---- cls_true zero-fill: 1024 blocks x 80KB contiguous slices (fire-and-forget) ----
    {
        const int blockid = (b * 8 + gs) * NCHUNK + chunk;        // 0..1023
        float4* cls4 = reinterpret_cast<float4*>(out) + (long long)blockid * 5120;
        const float4 z = make_float4(0.f, 0.f, 0.f, 0.f);
        #pragma unroll
        for (int i = 0; i < 20; i++) cls4[i * 256 + t] = z;
    }

    if (t < 8) {
        const int g = gs * 8 + t;
        const float* row = gt + (b * G_ + g) * 6;
        float cx = row[0], cy = row[1], w = row[2], h = row[3];
        s_valid[t] = (cx != -1.0f);
        s_gy1[t] = cy - 0.5f * h;  s_gx1[t] = cx - 0.5f * w;
        s_gy2[t] = cy + 0.5f * h;  s_gx2[t] = cx + 0.5f * w;
        s_ga[t]  = w * h;
    }
    __syncthreads();

    unsigned vmask = 0;
    #pragma unroll
    for (int g = 0; g < 8; g++) vmask |= (s_valid[g] ? (1u << g) : 0u);

    const int pbase = chunk * CHUNK_P + t;
    unsigned char* thm8 = (unsigned char*)g_thm;
    unsigned char* igm8 = (unsigned char*)g_igm;

    if (vmask == 0) {   // whole 8-gt slice invalid: masks are zero, no argmax work
        #pragma unroll
        for (int i = 0; i < CHUNK_P / 256; i++) {
            const long long p = pbase + i * 256;
            const long long byteoff = ((long long)b * P_ + p) * 8 + gs;
            thm8[byteoff] = 0; igm8[byteoff] = 0;
        }
        if (t < 8) g_part[(b * G_ + gs * 8 + t) * NCHUNK + chunk] = 0ull;
        return;
    }

    float bi[8], bueps[8]; int bx[8];
    #pragma unroll
    for (int g = 0; g < 8; g++) { bi[g] = -1.0f; bueps[g] = IOU_EPS; bx[g] = 0; }

    #pragma unroll
    for (int i = 0; i < CHUNK_P / 256; i++) {
        const int p = pbase + i * 256;
        const float4 pb = reinterpret_cast<const float4*>(pr)[p];
        const float py1 = pb.y - 0.5f * pb.w, px1 = pb.x - 0.5f * pb.z;
        const float py2 = pb.y + 0.5f * pb.w, px2 = pb.x + 0.5f * pb.z;
        const float pa  = pb.z * pb.w;
        unsigned thb = 0, igb = 0;
        #pragma unroll
        for (int g = 0; g < 8; g++) {
            float ih = fmaxf(fminf(s_gy2[g], py2) - fmaxf(s_gy1[g], py1), 0.0f);
            float iw = fmaxf(fminf(s_gx2[g], px2) - fmaxf(s_gx1[g], px1), 0.0f);
            float inter = iw * ih;
            float un = (s_ga[g] + pa) - inter;       // reference op order
            float uneps = un + IOU_EPS;
            if (inter >= 0.5f * uneps) thb |= 1u << g;   // iou >= 0.5 (proven form)
            if (inter >= 0.4f * uneps) igb |= 1u << g;   // iou >= 0.4 (proven form)
            // argmax via cross-mult; strict > with ascending p == first-max tie-break
            float lhs = inter * bueps[g];
            float rhs = bi[g] * uneps;
            if (lhs > rhs) { bi[g] = inter; bueps[g] = uneps; bx[g] = p; }
        }
        thb &= vmask; igb &= vmask;
        const long long byteoff = ((long long)b * P_ + p) * 8 + gs;
        thm8[byteoff] = (unsigned char)thb;
        igm8[byteoff] = (unsigned char)igb;
    }

    const unsigned FULL = 0xFFFFFFFFu;
    #pragma unroll
    for (int g = 0; g < 8; g++) {
        float i0 = bi[g], u0 = bueps[g]; int x0 = bx[g];
        #pragma unroll
        for (int off = 16; off; off >>= 1) {
            float oi = __shfl_down_sync(FULL, i0, off);
            float ou = __shfl_down_sync(FULL, u0, off);
            int   ox = __shfl_down_sync(FULL, x0, off);
            float lhs = oi * u0;
            float rhs = i0 * ou;
            if (lhs > rhs || (lhs == rhs && ox < x0)) { i0 = oi; u0 = ou; x0 = ox; }
        }
        if (lane == 0) { r_i[g][wid] = i0; r_u[g][wid] = u0; r_x[g][wid] = x0; }
    }
    __syncthreads();

    if (t < 8) {
        unsigned long long outv = 0ull;
        if (s_valid[t]) {
            float i0 = r_i[t][0], u0 = r_u[t][0]; int x0 = r_x[t][0];
            #pragma unroll
            for (int w2 = 1; w2 < 8; w2++) {
                float oi = r_i[t][w2], ou = r_u[t][w2]; int ox = r_x[t][w2];
                float lhs = oi * u0;
                float rhs = i0 * ou;
                if (lhs > rhs || (lhs == rhs && ox < x0)) { i0 = oi; u0 = ou; x0 = ox; }
            }
            float iou = __fdiv_rn(i0, u0);   // u0 already = union + eps; IEEE div
            outv = ((unsigned long long)__float_as_uint(iou) << 32) | (unsigned)(~x0);
        }
        g_part[(b * G_ + gs * 8 + t) * NCHUNK + chunk] = outv;
    }
}

// Pass 2: grid=(128,8), 256 thr. Sparse: masks + bit walks + loc/mask + single
// 1.0 scalar for matched predictions (cls region pre-zeroed by k_pass1).
__global__ void __launch_bounds__(256) k_out(const float* __restrict__ gt,
                                             const float* __restrict__ pr,
                                             float* __restrict__ out) {
    const int b = blockIdx.y;
    const int p0 = blockIdx.x * 256;
    const int t = threadIdx.x;
    const int p = p0 + t;

    // Prefetch per-p data FIRST so latency hides under the g_part reduction + barriers.
    const long long bp_ = (long long)b * P_ + p;
    const unsigned long long th64 = g_thm[bp_];
    const unsigned long long ig64 = g_igm[bp_];
    const float4 pb = reinterpret_cast<const float4*>(pr)[p];

    __shared__ float scx[G_], scy[G_], slw[G_], slhh[G_], slabv[G_];
    __shared__ unsigned long long s_gbe[256];   // bitmask of gts whose best_p == local p

    s_gbe[t] = 0ull;

    int bp = -1;
    if (t < G_) {
        const float* row = gt + (b * G_ + t) * 6;
        float cx = row[0], cy = row[1], w = row[2], h = row[3];
        float lab = row[4], conf = row[5];
        int validf = (cx != -1.0f);
        scx[t] = cx; scy[t] = cy;
        slw[t]  = (w > 0.0f) ? logf(fmaxf(w, 1e-20f)) : 0.0f;
        slhh[t] = (h > 0.0f) ? logf(fmaxf(h, 1e-20f)) : 0.0f;
        slabv[t] = lab;
        // reduce the 16 chunk partials -> global best_p for this gt
        unsigned long long best = 0ull;
        const unsigned long long* pp = g_part + (b * G_ + t) * NCHUNK;
        #pragma unroll
        for (int c = 0; c < NCHUNK; c++) {
            unsigned long long v = pp[c];
            best = (v > best) ? v : best;
        }
        bp = (int)(~(unsigned)(best & 0xFFFFFFFFull));   // empty -> -1
        if (!validf || !(conf > 0.0f)) bp = -1;          // "best" requires conf > 0
    }
    __syncthreads();
    if (t < G_ && bp >= p0 && bp < p0 + 256) atomicOr(&s_gbe[bp - p0], 1ull << t);
    __syncthreads();

    const bool ignore = (ig64 & ~th64) != 0ull;

    float W = 0.0f, Scx = 0.0f, Scy = 0.0f, Slw = 0.0f, Slh = 0.0f;
    int gth = -1;
    unsigned long long m = th64;
    if (m) {
        gth = 63 - __clzll(m);
        do {
            int g = __ffsll(m) - 1;
            m &= m - 1;
            W += 1.0f; Scx += scx[g]; Scy += scy[g]; Slw += slw[g]; Slh += slhh[g];
        } while (m);
    }

    // best-box contributions: ALL gts whose best_p == p add weight (can be >1)
    unsigned long long bm = s_gbe[t];
    int gbe = -1;
    if (bm) {
        gbe = 63 - __clzll(bm);           // winner = max g
        do {
            int g = __ffsll(bm) - 1;
            bm &= bm - 1;
            W += 1.0f; Scx += scx[g]; Scy += scy[g]; Slw += slw[g]; Slh += slhh[g];
        } while (bm);
    }

    const int win = (gbe >= 0) ? gbe : gth;
    const bool matched = (win >= 0);
    const int widx = matched ? win : 0;
    const int cid = matched ? (int)slabv[widx] : C_;
    const float mask = ignore ? -1.0f : (matched ? 0.0f : 1.0f);

    const float hcx = __fdividef(Scx - W * pb.x, pb.z);
    const float hcy = __fdividef(Scy - W * pb.y, pb.w);
    const float hw  = Slw - W * __logf(pb.z);
    const float hh  = Slh - W * __logf(pb.w);

    const long long CLS_SZ = (long long)B_ * P_ * C_;
    const long long LOC_SZ = (long long)B_ * P_ * 4;

    // loc_true: coalesced float4 per thread
    reinterpret_cast<float4*>(out + CLS_SZ)[bp_] = make_float4(hcx, hcy, hw, hh);
    // assign_mask: coalesced float per thread
    out[CLS_SZ + LOC_SZ + bp_] = mask;
    // cls_true: sparse — region pre-zeroed; write only the matched 1.0
    if (matched) out[bp_ * C_ + cid] = 1.0f;
}

extern "C" void kernel_launch(void* const* d_in, const int* in_sizes, int n_in,
                              void* d_out, int out_size) {
    const float* gt = (const float*)d_in[0];   // [8, 64, 6]
    const float* pr = (const float*)d_in[1];   // [8, 32768, 4] (broadcast; batch 0 used)
    float* out = (float*)d_out;                // cls[8,32768,80] | loc[8,32768,4] | mask[8,32768,1]

    k_pass1<<<dim3(NCHUNK, 8, 8), 256>>>(gt, pr, out);
    k_out<<<dim3(P_ / 256, B_), 256>>>(gt, pr, out);
}

// round 13
// speedup vs baseline: 1.6724x; 1.1143x over previous
#include <cuda_runtime.h>
#include <cuda_bf16.h>
#include <cstdint>

#define IOU_EPS 1e-5f
#define B_  8
#define G_  64
#define P_  32768
#define C_  80
#define NCHUNK 16
#define CHUNK_P (P_ / NCHUNK)   // 2048
#define PPB 1024                // predictions per k_out block

// Per-chunk argmax partials. packed = (iou_bits << 32) | ~idx  (u64 max => max iou,
// tie -> smaller idx, matching jnp.argmax first-index tie-break). 0 == "no candidate".
__device__ unsigned long long g_part[B_ * G_ * NCHUNK];
// Combined per-(b,p,gs) masks: u16 = th_byte | (ig_byte << 8). 16B per (b,p) -> uint4.
__device__ __align__(16) unsigned short g_msk[B_ * P_ * 8];

// Pass 1: grid=(16,8,8)=(chunk,gs,b), 256 thr. Per block: 8 gts x 2048 prs.
// Computes per-gt argmax partials AND per-(p,gs) combined th/ig mask u16, AND
// zero-fills this block's 80KB slice of cls_true (sparse 1.0s written by k_out).
__global__ void __launch_bounds__(256) k_pass1(const float* __restrict__ gt,
                                               const float* __restrict__ pr,
                                               float* __restrict__ out) {
    const int b = blockIdx.z, gs = blockIdx.y, chunk = blockIdx.x;
    const int t = threadIdx.x, lane = t & 31, wid = t >> 5;
    __shared__ float r_i[8][8], r_u[8][8];
    __shared__ int   r_x[8][8];

    // ---- cls_true zero-fill: 1024 blocks x 80KB contiguous slices ----
    {
        const int blockid = (b * 8 + gs) * NCHUNK + chunk;        // 0..1023
        float4* cls4 = reinterpret_cast<float4*>(out) + (long long)blockid * 5120;
        const float4 z = make_float4(0.f, 0.f, 0.f, 0.f);
        #pragma unroll
        for (int i = 0; i < 20; i++) cls4[i * 256 + t] = z;
    }

    // ---- gt slice -> registers (broadcast loads, L1-hit after first warp) ----
    float gy1[8], gx1[8], gy2[8], gx2[8], gav[8];
    unsigned vmask = 0;
    {
        const float* grow = gt + (b * G_ + gs * 8) * 6;
        #pragma unroll
        for (int g = 0; g < 8; g++) {
            const float2 c01 = *reinterpret_cast<const float2*>(grow + g * 6);      // cx, cy
            const float2 c23 = *reinterpret_cast<const float2*>(grow + g * 6 + 2);  // w, h
            const float cx = c01.x, cy = c01.y, w = c23.x, h = c23.y;
            if (cx != -1.0f) vmask |= 1u << g;
            gy1[g] = cy - 0.5f * h;  gx1[g] = cx - 0.5f * w;
            gy2[g] = cy + 0.5f * h;  gx2[g] = cx + 0.5f * w;
            gav[g] = w * h;
        }
    }

    const int pbase = chunk * CHUNK_P + t;
    unsigned short* msk = g_msk;

    if (vmask == 0) {   // whole 8-gt slice invalid: masks zero, no argmax work
        #pragma unroll
        for (int i = 0; i < CHUNK_P / 256; i++) {
            const long long p = pbase + i * 256;
            msk[((long long)b * P_ + p) * 8 + gs] = 0;
        }
        if (t < 8) g_part[(b * G_ + gs * 8 + t) * NCHUNK + chunk] = 0ull;
        return;
    }

    float bi[8], bueps[8]; int bx[8];
    #pragma unroll
    for (int g = 0; g < 8; g++) { bi[g] = -1.0f; bueps[g] = IOU_EPS; bx[g] = 0; }

    #pragma unroll
    for (int i = 0; i < CHUNK_P / 256; i++) {
        const int p = pbase + i * 256;
        const float4 pb = reinterpret_cast<const float4*>(pr)[p];
        const float py1 = pb.y - 0.5f * pb.w, px1 = pb.x - 0.5f * pb.z;
        const float py2 = pb.y + 0.5f * pb.w, px2 = pb.x + 0.5f * pb.z;
        const float pa  = pb.z * pb.w;
        unsigned thb = 0, igb = 0;
        #pragma unroll
        for (int g = 0; g < 8; g++) {
            float ih = fmaxf(fminf(gy2[g], py2) - fmaxf(gy1[g], py1), 0.0f);
            float iw = fmaxf(fminf(gx2[g], px2) - fmaxf(gx1[g], px1), 0.0f);
            float inter = iw * ih;
            float un = (gav[g] + pa) - inter;        // reference op order
            float uneps = un + IOU_EPS;
            if (inter >= 0.5f * uneps) thb |= 1u << g;   // iou >= 0.5 (proven form)
            if (inter >= 0.4f * uneps) igb |= 1u << g;   // iou >= 0.4 (proven form)
            // argmax via cross-mult; strict > with ascending p == first-max tie-break
            float lhs = inter * bueps[g];
            float rhs = bi[g] * uneps;
            if (lhs > rhs) { bi[g] = inter; bueps[g] = uneps; bx[g] = p; }
        }
        thb &= vmask; igb &= vmask;
        msk[((long long)b * P_ + p) * 8 + gs] = (unsigned short)(thb | (igb << 8));
    }

    const unsigned FULL = 0xFFFFFFFFu;
    #pragma unroll
    for (int g = 0; g < 8; g++) {
        float i0 = bi[g], u0 = bueps[g]; int x0 = bx[g];
        #pragma unroll
        for (int off = 16; off; off >>= 1) {
            float oi = __shfl_down_sync(FULL, i0, off);
            float ou = __shfl_down_sync(FULL, u0, off);
            int   ox = __shfl_down_sync(FULL, x0, off);
            float lhs = oi * u0;
            float rhs = i0 * ou;
            if (lhs > rhs || (lhs == rhs && ox < x0)) { i0 = oi; u0 = ou; x0 = ox; }
        }
        if (lane == 0) { r_i[g][wid] = i0; r_u[g][wid] = u0; r_x[g][wid] = x0; }
    }
    __syncthreads();

    if (t < 8) {
        unsigned long long outv = 0ull;
        if ((vmask >> t) & 1u) {
            float i0 = r_i[t][0], u0 = r_u[t][0]; int x0 = r_x[t][0];
            #pragma unroll
            for (int w2 = 1; w2 < 8; w2++) {
                float oi = r_i[t][w2], ou = r_u[t][w2]; int ox = r_x[t][w2];
                float lhs = oi * u0;
                float rhs = i0 * ou;
                if (lhs > rhs || (lhs == rhs && ox < x0)) { i0 = oi; u0 = ou; x0 = ox; }
            }
            float iou = __fdiv_rn(i0, u0);   // u0 already = union + eps; IEEE div
            outv = ((unsigned long long)__float_as_uint(iou) << 32) | (unsigned)(~x0);
        }
        g_part[(b * G_ + gs * 8 + t) * NCHUNK + chunk] = outv;
    }
}

// Pass 2: grid=(32,8), 256 thr, 4 predictions per thread. Sparse outputs.
__global__ void __launch_bounds__(256) k_out(const float* __restrict__ gt,
                                             const float* __restrict__ pr,
                                             float* __restrict__ out) {
    const int b = blockIdx.y;
    const int p0 = blockIdx.x * PPB;
    const int t = threadIdx.x;

    __shared__ float scx[G_], scy[G_], slw[G_], slhh[G_], slabv[G_];
    __shared__ int   s_vc[G_], s_bp[G_];
    __shared__ unsigned long long s_gbe[PPB];   // bitmask of gts whose best_p == local p

    #pragma unroll
    for (int k = 0; k < PPB / 256; k++) s_gbe[t + k * 256] = 0ull;

    // Prefetch per-p data first (MLP 8) so latency hides under reductions/barriers.
    uint4  mv[4];
    float4 pv[4];
    #pragma unroll
    for (int k = 0; k < 4; k++) {
        const int p = p0 + k * 256 + t;
        mv[k] = reinterpret_cast<const uint4*>(g_msk)[(long long)b * P_ + p];
        pv[k] = reinterpret_cast<const float4*>(pr)[p];
    }

    if (t < G_) {
        const float* row = gt + (b * G_ + t) * 6;
        float cx = row[0], cy = row[1], w = row[2], h = row[3];
        float lab = row[4], conf = row[5];
        scx[t] = cx; scy[t] = cy;
        slw[t]  = (w > 0.0f) ? logf(fmaxf(w, 1e-20f)) : 0.0f;
        slhh[t] = (h > 0.0f) ? logf(fmaxf(h, 1e-20f)) : 0.0f;
        slabv[t] = lab;
        s_vc[t] = (cx != -1.0f) && (conf > 0.0f);
    }

    // Parallel g_part reduction: thread quad (t>>2 = g, t&3 = quarter) -> 4 u64 each.
    {
        const int g = t >> 2, q = t & 3;
        const unsigned long long* pp = g_part + (b * G_ + g) * NCHUNK + q * 4;
        unsigned long long m0 = pp[0], m1 = pp[1], m2 = pp[2], m3 = pp[3];
        unsigned long long m = m0 > m1 ? m0 : m1;
        unsigned long long n = m2 > m3 ? m2 : m3;
        m = m > n ? m : n;
        unsigned long long o = __shfl_down_sync(0xFFFFFFFFu, m, 2);
        m = m > o ? m : o;
        o = __shfl_down_sync(0xFFFFFFFFu, m, 1);
        m = m > o ? m : o;
        if (q == 0) s_bp[g] = (int)(~(unsigned)(m & 0xFFFFFFFFull));  // empty -> -1
    }
    __syncthreads();
    if (t < G_) {
        const int bp = s_vc[t] ? s_bp[t] : -1;   // "best" requires valid && conf > 0
        if (bp >= p0 && bp < p0 + PPB) atomicOr(&s_gbe[bp - p0], 1ull << t);
    }
    __syncthreads();

    const long long CLS_SZ = (long long)B_ * P_ * C_;
    const long long LOC_SZ = (long long)B_ * P_ * 4;

    #pragma unroll
    for (int k = 0; k < 4; k++) {
        const int p = p0 + k * 256 + t;
        const long long bp_ = (long long)b * P_ + p;
        const uint4 v = mv[k];
        // de-interleave th (even bytes) / ig (odd bytes)
        const unsigned th_lo = __byte_perm(v.x, v.y, 0x6420);
        const unsigned th_hi = __byte_perm(v.z, v.w, 0x6420);
        const unsigned ig_lo = __byte_perm(v.x, v.y, 0x7531);
        const unsigned ig_hi = __byte_perm(v.z, v.w, 0x7531);
        const unsigned long long th64 = ((unsigned long long)th_hi << 32) | th_lo;
        const unsigned long long ig64 = ((unsigned long long)ig_hi << 32) | ig_lo;
        const float4 pb = pv[k];

        const bool ignore = (ig64 & ~th64) != 0ull;

        float W = 0.0f, Scx = 0.0f, Scy = 0.0f, Slw = 0.0f, Slh = 0.0f;
        int gth = -1;
        unsigned long long m = th64;
        if (m) {
            gth = 63 - __clzll(m);
            do {
                int g = __ffsll(m) - 1;
                m &= m - 1;
                W += 1.0f; Scx += scx[g]; Scy += scy[g]; Slw += slw[g]; Slh += slhh[g];
            } while (m);
        }

        // best-box contributions: ALL gts whose best_p == p add weight (can be >1)
        unsigned long long bm = s_gbe[k * 256 + t];
        int gbe = -1;
        if (bm) {
            gbe = 63 - __clzll(bm);           // winner = max g
            do {
                int g = __ffsll(bm) - 1;
                bm &= bm - 1;
                W += 1.0f; Scx += scx[g]; Scy += scy[g]; Slw += slw[g]; Slh += slhh[g];
            } while (bm);
        }

        const int win = (gbe >= 0) ? gbe : gth;
        const bool matched = (win >= 0);
        const int widx = matched ? win : 0;
        const int cid = matched ? (int)slabv[widx] : C_;
        const float mask = ignore ? -1.0f : (matched ? 0.0f : 1.0f);

        const float hcx = __fdividef(Scx - W * pb.x, pb.z);
        const float hcy = __fdividef(Scy - W * pb.y, pb.w);
        const float hw  = Slw - W * __logf(pb.z);
        const float hh  = Slh - W * __logf(pb.w);

        // loc_true: coalesced float4; assign_mask: coalesced float
        reinterpret_cast<float4*>(out + CLS_SZ)[bp_] = make_float4(hcx, hcy, hw, hh);
        out[CLS_SZ + LOC_SZ + bp_] = mask;
        // cls_true: sparse — region pre-zeroed by k_pass1; write only the matched 1.0
        if (matched) out[bp_ * C_ + cid] = 1.0f;
    }
}

extern "C" void kernel_launch(void* const* d_in, const int* in_sizes, int n_in,
                              void* d_out, int out_size) {
    const float* gt = (const float*)d_in[0];   // [8, 64, 6]
    const float* pr = (const float*)d_in[1];   // [8, 32768, 4] (broadcast; batch 0 used)
    float* out = (float*)d_out;                // cls[8,32768,80] | loc[8,32768,4] | mask[8,32768,1]

    k_pass1<<<dim3(NCHUNK, 8, 8), 256>>>(gt, pr, out);
    k_out<<<dim3(P_ / PPB, B_), 256>>>(gt, pr, out);
}

// round 16
// speedup vs baseline: 1.7865x; 1.0683x over previous
#include <cuda_runtime.h>
#include <cuda_bf16.h>
#include <cstdint>

#define IOU_EPS 1e-5f
#define B_  8
#define G_  64
#define P_  32768
#define C_  80
#define NCHUNK 16
#define CHUNK_P (P_ / NCHUNK)   // 2048
#define PPB 512                 // predictions per k_out block

// Per-chunk argmax partials. packed = (iou_bits << 32) | ~idx  (u64 max => max iou,
// tie -> smaller idx, matching jnp.argmax first-index tie-break). 0 == "no candidate".
__device__ unsigned long long g_part[B_ * G_ * NCHUNK];
// PLANE-MAJOR masks: g_msk[gs][b*P+p] = u16 (th_byte | ig_byte<<8) for gts gs*8..gs*8+7.
// Pass1 (fixed gs,b) stores 32 consecutive u16 per warp = 64B coalesced.
__device__ __align__(16) unsigned short g_msk[8][B_ * P_];

// Pass 1: grid=(16,8,8)=(chunk,gs,b), 256 thr. Per block: 8 gts x 2048 prs.
__global__ void __launch_bounds__(256) k_pass1(const float* __restrict__ gt,
                                               const float* __restrict__ pr,
                                               float* __restrict__ out) {
    const int b = blockIdx.z, gs = blockIdx.y, chunk = blockIdx.x;
    const int t = threadIdx.x, lane = t & 31, wid = t >> 5;
    __shared__ float r_i[8][8], r_u[8][8];
    __shared__ int   r_x[8][8];

    // ---- cls_true zero-fill: 1024 blocks x 80KB contiguous slices ----
    {
        const int blockid = (b * 8 + gs) * NCHUNK + chunk;        // 0..1023
        float4* cls4 = reinterpret_cast<float4*>(out) + (long long)blockid * 5120;
        const float4 z = make_float4(0.f, 0.f, 0.f, 0.f);
        #pragma unroll
        for (int i = 0; i < 20; i++) cls4[i * 256 + t] = z;
    }

    // ---- gt slice -> registers (broadcast loads, L1-hit after first warp) ----
    float gy1[8], gx1[8], gy2[8], gx2[8], gav[8];
    unsigned vmask = 0;
    {
        const float* grow = gt + (b * G_ + gs * 8) * 6;
        #pragma unroll
        for (int g = 0; g < 8; g++) {
            const float2 c01 = *reinterpret_cast<const float2*>(grow + g * 6);      // cx, cy
            const float2 c23 = *reinterpret_cast<const float2*>(grow + g * 6 + 2);  // w, h
            const float cx = c01.x, cy = c01.y, w = c23.x, h = c23.y;
            if (cx != -1.0f) vmask |= 1u << g;
            gy1[g] = cy - 0.5f * h;  gx1[g] = cx - 0.5f * w;
            gy2[g] = cy + 0.5f * h;  gx2[g] = cx + 0.5f * w;
            gav[g] = w * h;
        }
    }

    unsigned short* mrow = &g_msk[gs][(long long)b * P_ + chunk * CHUNK_P + t];

    if (vmask == 0) {   // whole 8-gt slice invalid: masks zero, no argmax work
        #pragma unroll
        for (int i = 0; i < CHUNK_P / 256; i++) mrow[i * 256] = 0;
        if (t < 8) g_part[(b * G_ + gs * 8 + t) * NCHUNK + chunk] = 0ull;
        return;
    }

    float bi[8], bueps[8]; int bx[8];
    #pragma unroll
    for (int g = 0; g < 8; g++) { bi[g] = -1.0f; bueps[g] = IOU_EPS; bx[g] = 0; }

    const int pbase = chunk * CHUNK_P + t;
    #pragma unroll
    for (int i = 0; i < CHUNK_P / 256; i++) {
        const int p = pbase + i * 256;
        const float4 pb = reinterpret_cast<const float4*>(pr)[p];
        const float py1 = pb.y - 0.5f * pb.w, px1 = pb.x - 0.5f * pb.z;
        const float py2 = pb.y + 0.5f * pb.w, px2 = pb.x + 0.5f * pb.z;
        const float pa  = pb.z * pb.w;
        unsigned thb = 0, igb = 0;
        #pragma unroll
        for (int g = 0; g < 8; g++) {
            float ih = fmaxf(fminf(gy2[g], py2) - fmaxf(gy1[g], py1), 0.0f);
            float iw = fmaxf(fminf(gx2[g], px2) - fmaxf(gx1[g], px1), 0.0f);
            float inter = iw * ih;
            float un = (gav[g] + pa) - inter;        // reference op order
            float uneps = un + IOU_EPS;
            if (inter >= 0.5f * uneps) thb |= 1u << g;   // iou >= 0.5 (proven form)
            if (inter >= 0.4f * uneps) igb |= 1u << g;   // iou >= 0.4 (proven form)
            // argmax via cross-mult; strict > with ascending p == first-max tie-break
            float lhs = inter * bueps[g];
            float rhs = bi[g] * uneps;
            if (lhs > rhs) { bi[g] = inter; bueps[g] = uneps; bx[g] = p; }
        }
        thb &= vmask; igb &= vmask;
        mrow[i * 256] = (unsigned short)(thb | (igb << 8));   // coalesced: 64B/warp
    }

    const unsigned FULL = 0xFFFFFFFFu;
    #pragma unroll
    for (int g = 0; g < 8; g++) {
        float i0 = bi[g], u0 = bueps[g]; int x0 = bx[g];
        #pragma unroll
        for (int off = 16; off; off >>= 1) {
            float oi = __shfl_down_sync(FULL, i0, off);
            float ou = __shfl_down_sync(FULL, u0, off);
            int   ox = __shfl_down_sync(FULL, x0, off);
            float lhs = oi * u0;
            float rhs = i0 * ou;
            if (lhs > rhs || (lhs == rhs && ox < x0)) { i0 = oi; u0 = ou; x0 = ox; }
        }
        if (lane == 0) { r_i[g][wid] = i0; r_u[g][wid] = u0; r_x[g][wid] = x0; }
    }
    __syncthreads();

    if (t < 8) {
        unsigned long long outv = 0ull;
        if ((vmask >> t) & 1u) {
            float i0 = r_i[t][0], u0 = r_u[t][0]; int x0 = r_x[t][0];
            #pragma unroll
            for (int w2 = 1; w2 < 8; w2++) {
                float oi = r_i[t][w2], ou = r_u[t][w2]; int ox = r_x[t][w2];
                float lhs = oi * u0;
                float rhs = i0 * ou;
                if (lhs > rhs || (lhs == rhs && ox < x0)) { i0 = oi; u0 = ou; x0 = ox; }
            }
            float iou = __fdiv_rn(i0, u0);   // u0 already = union + eps; IEEE div
            outv = ((unsigned long long)__float_as_uint(iou) << 32) | (unsigned)(~x0);
        }
        g_part[(b * G_ + gs * 8 + t) * NCHUNK + chunk] = outv;
    }
}

// Gather byte `sel` of four u32s into one u32 (3 PRMT).
__device__ __forceinline__ unsigned gather4(unsigned a, unsigned b, unsigned c,
                                            unsigned d, unsigned sel) {
    unsigned s0 = __byte_perm(a, b, sel);
    unsigned s1 = __byte_perm(c, d, sel);
    return __byte_perm(s0, s1, 0x5410);
}

// Pass 2: grid=(64,8), 256 thr, 2 CONSECUTIVE predictions per thread.
__global__ void __launch_bounds__(256) k_out(const float* __restrict__ gt,
                                             const float* __restrict__ pr,
                                             float* __restrict__ out) {
    const int b = blockIdx.y;
    const int p0 = blockIdx.x * PPB;
    const int t = threadIdx.x;
    const int p = p0 + 2 * t;                 // even; thread covers p, p+1

    __shared__ float scx[G_], scy[G_], slw[G_], slhh[G_], slabv[G_];
    __shared__ int   s_vc[G_], s_bp[G_];
    __shared__ unsigned long long s_gbe[PPB];   // bitmask of gts whose best_p == local p

    s_gbe[2 * t] = 0ull; s_gbe[2 * t + 1] = 0ull;

    // Prefetch per-p data first so latency hides under reductions/barriers.
    unsigned mv[8];
    const long long bP = (long long)b * P_;
    #pragma unroll
    for (int gs = 0; gs < 8; gs++)
        mv[gs] = *reinterpret_cast<const unsigned*>(&g_msk[gs][bP + p]);  // 2 p's / load
    float4 pv[2];
    pv[0] = reinterpret_cast<const float4*>(pr)[p];
    pv[1] = reinterpret_cast<const float4*>(pr)[p + 1];

    if (t < G_) {
        const float* row = gt + (b * G_ + t) * 6;
        float cx = row[0], cy = row[1], w = row[2], h = row[3];
        float lab = row[4], conf = row[5];
        scx[t] = cx; scy[t] = cy;
        slw[t]  = (w > 0.0f) ? logf(fmaxf(w, 1e-20f)) : 0.0f;
        slhh[t] = (h > 0.0f) ? logf(fmaxf(h, 1e-20f)) : 0.0f;
        slabv[t] = lab;
        s_vc[t] = (cx != -1.0f) && (conf > 0.0f);
    }

    // Parallel g_part reduction: thread quad (t>>2 = g, t&3 = quarter) -> 4 u64 each.
    {
        const int g = t >> 2, q = t & 3;
        const unsigned long long* pp = g_part + (b * G_ + g) * NCHUNK + q * 4;
        unsigned long long m0 = pp[0], m1 = pp[1], m2 = pp[2], m3 = pp[3];
        unsigned long long m = m0 > m1 ? m0 : m1;
        unsigned long long n = m2 > m3 ? m2 : m3;
        m = m > n ? m : n;
        unsigned long long o = __shfl_down_sync(0xFFFFFFFFu, m, 2);
        m = m > o ? m : o;
        o = __shfl_down_sync(0xFFFFFFFFu, m, 1);
        m = m > o ? m : o;
        if (q == 0) s_bp[g] = (int)(~(unsigned)(m & 0xFFFFFFFFull));  // empty -> -1
    }
    __syncthreads();
    if (t < G_) {
        const int bp = s_vc[t] ? s_bp[t] : -1;   // "best" requires valid && conf > 0
        if (bp >= p0 && bp < p0 + PPB) atomicOr(&s_gbe[bp - p0], 1ull << t);
    }
    __syncthreads();

    // Assemble th/ig u64 masks for both p's via byte-gather trees.
    // Plane u32 layout: [th_even, ig_even, th_odd, ig_odd] bytes.
    unsigned long long th64[2], ig64[2];
    {
        unsigned lo, hi;
        lo = gather4(mv[0], mv[1], mv[2], mv[3], 0x0040);
        hi = gather4(mv[4], mv[5], mv[6], mv[7], 0x0040);
        th64[0] = ((unsigned long long)hi << 32) | lo;
        lo = gather4(mv[0], mv[1], mv[2], mv[3], 0x0051);
        hi = gather4(mv[4], mv[5], mv[6], mv[7], 0x0051);
        ig64[0] = ((unsigned long long)hi << 32) | lo;
        lo = gather4(mv[0], mv[1], mv[2], mv[3], 0x0062);
        hi = gather4(mv[4], mv[5], mv[6], mv[7], 0x0062);
        th64[1] = ((unsigned long long)hi << 32) | lo;
        lo = gather4(mv[0], mv[1], mv[2], mv[3], 0x0073);
        hi = gather4(mv[4], mv[5], mv[6], mv[7], 0x0073);
        ig64[1] = ((unsigned long long)hi << 32) | lo;
    }

    const long long CLS_SZ = (long long)B_ * P_ * C_;
    const long long LOC_SZ = (long long)B_ * P_ * 4;
    float mask2[2];

    #pragma unroll
    for (int k = 0; k < 2; k++) {
        const long long bp_ = bP + p + k;
        const float4 pb = pv[k];
        const bool ignore = (ig64[k] & ~th64[k]) != 0ull;

        float W = 0.0f, Scx = 0.0f, Scy = 0.0f, Slw = 0.0f, Slh = 0.0f;
        int gth = -1;
        unsigned long long m = th64[k];
        if (m) {
            gth = 63 - __clzll(m);
            do {
                int g = __ffsll(m) - 1;
                m &= m - 1;
                W += 1.0f; Scx += scx[g]; Scy += scy[g]; Slw += slw[g]; Slh += slhh[g];
            } while (m);
        }

        // best-box contributions: ALL gts whose best_p == p add weight (can be >1)
        unsigned long long bm = s_gbe[2 * t + k];
        int gbe = -1;
        if (bm) {
            gbe = 63 - __clzll(bm);           // winner = max g
            do {
                int g = __ffsll(bm) - 1;
                bm &= bm - 1;
                W += 1.0f; Scx += scx[g]; Scy += scy[g]; Slw += slw[g]; Slh += slhh[g];
            } while (bm);
        }

        const int win = (gbe >= 0) ? gbe : gth;
        const bool matched = (win >= 0);
        const int widx = matched ? win : 0;
        const int cid = matched ? (int)slabv[widx] : C_;
        mask2[k] = ignore ? -1.0f : (matched ? 0.0f : 1.0f);

        const float hcx = __fdividef(Scx - W * pb.x, pb.z);
        const float hcy = __fdividef(Scy - W * pb.y, pb.w);
        const float hw  = Slw - W * __logf(pb.z);
        const float hh  = Slh - W * __logf(pb.w);

        // loc_true: adjacent float4 stores (thread covers 32B contiguous)
        reinterpret_cast<float4*>(out + CLS_SZ)[bp_] = make_float4(hcx, hcy, hw, hh);
        // cls_true: sparse — region pre-zeroed by k_pass1; write only the matched 1.0
        if (matched) out[bp_ * C_ + cid] = 1.0f;
    }
    // assign_mask: one STG.64 for both p's
    *reinterpret_cast<float2*>(out + CLS_SZ + LOC_SZ + bP + p) =
        make_float2(mask2[0], mask2[1]);
}

extern "C" void kernel_launch(void* const* d_in, const int* in_sizes, int n_in,
                              void* d_out, int out_size) {
    const float* gt = (const float*)d_in[0];   // [8, 64, 6]
    const float* pr = (const float*)d_in[1];   // [8, 32768, 4] (broadcast; batch 0 used)
    float* out = (float*)d_out;                // cls[8,32768,80] | loc[8,32768,4] | mask[8,32768,1]

    k_pass1<<<dim3(NCHUNK, 8, 8), 256>>>(gt, pr, out);
    k_out<<<dim3(P_ / PPB, B_), 256>>>(gt, pr, out);
}